// round 2
// baseline (speedup 1.0000x reference)
#include <cuda_runtime.h>

// BahdanauAttention: B=64, S=2048, D=512, U=256
//   pv    = values @ W1 + b1              [B,S,U]
//   pq    = query  @ W2 + b2              [B,1,U]
//   score = tanh(pv + pq) @ V + bV        [B,S,1]   (bV cancels in softmax)
//   attn  = softmax(score, axis=S)
//   ctx   = sum_s attn * values           [B,D]
// out = [ctx (B*D floats) | attn (B*S floats)]

#define NB 64
#define NS 2048
#define ND 512
#define NU 256

#define BM 64
#define BK 16

// scratch (no allocations allowed)
__device__ __align__(16) float g_pq[NB * NU];        // query@W2 + b2 + b1
__device__ __align__(16) float g_part[NB * 8 * ND];  // context partial sums

// ---------------------------------------------------------------------------
// Kernel A: pq[b,u] = sum_d query[b,d]*W2[d,u] + b2[u] + b1[u]
// grid = 64 (one per b), 256 threads (one per u)
// ---------------------------------------------------------------------------
__global__ void pq_kernel(const float* __restrict__ query,
                          const float* __restrict__ W2,
                          const float* __restrict__ b2,
                          const float* __restrict__ b1) {
    __shared__ float q[ND];
    int b = blockIdx.x;
    for (int i = threadIdx.x; i < ND; i += blockDim.x) q[i] = query[b * ND + i];
    __syncthreads();
    int u = threadIdx.x;
    float acc = b2[u] + b1[u];
#pragma unroll 8
    for (int d = 0; d < ND; d++) acc += q[d] * W2[d * NU + u];
    g_pq[b * NU + u] = acc;
}

// ---------------------------------------------------------------------------
// Kernel B: the 34.4 GFLOP GEMM + fused tanh/V epilogue -> raw scores
// C[row, u] = values_flat[row,:]@W1[:,u];  score[row] = sum_u tanh(C+pq)*V[u]
// Block: 64 rows x 256 u, 256 threads, 8x8 microtile per thread.
// Thread (tx,ty) owns rows ty*8..+7 and u in {tx*4..+3} U {128+tx*4..+3}
//   (split-u mapping -> conflict-free LDS.128 of the B fragment: lanes 0..7
//    cover smem words 0..31 exactly once).
// Warp (fixed ty) covers all 256 u for its rows -> per-row score reduces with
// a single warp shuffle tree. grid = (B*S)/64 = 2048 blocks; each block lies
// inside one batch (S % 64 == 0).
// ---------------------------------------------------------------------------
__global__ __launch_bounds__(256, 2) void score_kernel(
    const float* __restrict__ values, const float* __restrict__ W1,
    const float* __restrict__ V, float* __restrict__ score_out) {
    __shared__ float As[BK][BM];   // A transposed: As[k][row]
    __shared__ float Bs[BK][NU];   // W1 tile

    int tid = threadIdx.x;
    int tx = tid & 31;   // u fragments at tx*4 and 128+tx*4
    int ty = tid >> 5;   // rows ty*8..ty*8+7
    int rowBase = blockIdx.x * BM;
    int b = rowBase / NS;
    const float* A = values + (size_t)rowBase * ND;

    float acc[8][8];
#pragma unroll
    for (int i = 0; i < 8; i++)
#pragma unroll
        for (int j = 0; j < 8; j++) acc[i][j] = 0.f;

    int a_row = tid >> 2;        // 0..63
    int a_kk  = (tid & 3) * 4;   // 0,4,8,12

    for (int k0 = 0; k0 < ND; k0 += BK) {
        // stage A tile (64 rows x 16 k), transposed into smem
        float4 av = *(const float4*)(A + (size_t)a_row * ND + k0 + a_kk);
        As[a_kk + 0][a_row] = av.x;
        As[a_kk + 1][a_row] = av.y;
        As[a_kk + 2][a_row] = av.z;
        As[a_kk + 3][a_row] = av.w;
        // stage B tile (16 k x 256 u): 1024 float4s, 4 per thread, coalesced
#pragma unroll
        for (int i = 0; i < 4; i++) {
            int idx = tid + i * 256;        // float4 index 0..1023
            int kr  = idx >> 6;             // 0..15
            int nc  = (idx & 63) * 4;       // 0..252
            *(float4*)&Bs[kr][nc] = *(const float4*)(W1 + (size_t)(k0 + kr) * NU + nc);
        }
        __syncthreads();
#pragma unroll
        for (int kk = 0; kk < BK; kk++) {
            float a[8], bb[8];
            *(float4*)&a[0]  = *(float4*)&As[kk][ty * 8];       // broadcast
            *(float4*)&a[4]  = *(float4*)&As[kk][ty * 8 + 4];   // broadcast
            *(float4*)&bb[0] = *(float4*)&Bs[kk][tx * 4];       // conflict-free
            *(float4*)&bb[4] = *(float4*)&Bs[kk][128 + tx * 4]; // conflict-free
#pragma unroll
            for (int i = 0; i < 8; i++)
#pragma unroll
                for (int j = 0; j < 8; j++) acc[i][j] += a[i] * bb[j];
        }
        __syncthreads();
    }

    // epilogue: score contribution, then warp-reduce over tx per row
    const float* pq = g_pq + b * NU;
    float vv[8], pp[8];
    *(float4*)&vv[0] = *(const float4*)(V + tx * 4);
    *(float4*)&vv[4] = *(const float4*)(V + 128 + tx * 4);
    *(float4*)&pp[0] = *(const float4*)(pq + tx * 4);
    *(float4*)&pp[4] = *(const float4*)(pq + 128 + tx * 4);

#pragma unroll
    for (int i = 0; i < 8; i++) {
        float p = 0.f;
#pragma unroll
        for (int j = 0; j < 8; j++) p += tanhf(acc[i][j] + pp[j]) * vv[j];
#pragma unroll
        for (int off = 16; off > 0; off >>= 1)
            p += __shfl_xor_sync(0xffffffffu, p, off);
        if (tx == 0) score_out[rowBase + ty * 8 + i] = p;
    }
}

// ---------------------------------------------------------------------------
// Kernel C: in-place softmax over S per batch. grid=64, 256 threads, 8 elems/thr
// ---------------------------------------------------------------------------
__global__ void softmax_kernel(float* __restrict__ attn) {
    __shared__ float red[256];
    int b = blockIdx.x, tid = threadIdx.x;
    float* p = attn + (size_t)b * NS;
    float v[8];
    float m = -1e30f;
#pragma unroll
    for (int j = 0; j < 8; j++) {
        v[j] = p[tid + j * 256];
        m = fmaxf(m, v[j]);
    }
    red[tid] = m;
    __syncthreads();
    for (int o = 128; o > 0; o >>= 1) {
        if (tid < o) red[tid] = fmaxf(red[tid], red[tid + o]);
        __syncthreads();
    }
    m = red[0];
    __syncthreads();
    float s = 0.f;
#pragma unroll
    for (int j = 0; j < 8; j++) {
        v[j] = __expf(v[j] - m);
        s += v[j];
    }
    red[tid] = s;
    __syncthreads();
    for (int o = 128; o > 0; o >>= 1) {
        if (tid < o) red[tid] += red[tid + o];
        __syncthreads();
    }
    float inv = 1.f / red[0];
#pragma unroll
    for (int j = 0; j < 8; j++) p[tid + j * 256] = v[j] * inv;
}

// ---------------------------------------------------------------------------
// Kernel D: context partials. Deterministic fixed-order reduction (no atomics).
// grid = 64 b * 8 s-chunks * 4 d-chunks = 2048 blocks, 128 threads.
// ---------------------------------------------------------------------------
__global__ __launch_bounds__(128) void ctx_part_kernel(
    const float* __restrict__ values, const float* __restrict__ attn) {
    __shared__ float a[256];
    int blk = blockIdx.x;
    int b  = blk >> 5;
    int sc = (blk >> 2) & 7;
    int dc = blk & 3;
    int tid = threadIdx.x;
    a[tid]       = attn[(size_t)b * NS + sc * 256 + tid];
    a[tid + 128] = attn[(size_t)b * NS + sc * 256 + tid + 128];
    __syncthreads();
    int d = dc * 128 + tid;
    const float* vp = values + ((size_t)b * NS + (size_t)sc * 256) * ND + d;
    float acc = 0.f;
#pragma unroll 8
    for (int s = 0; s < 256; s++) acc += a[s] * vp[(size_t)s * ND];
    g_part[((size_t)b * 8 + sc) * ND + d] = acc;
}

// Kernel E: sum the 8 s-chunk partials -> context
__global__ void ctx_reduce_kernel(float* __restrict__ ctx) {
    int idx = blockIdx.x * 256 + threadIdx.x;  // 0..32767
    int b = idx >> 9, d = idx & 511;
    float s = 0.f;
#pragma unroll
    for (int sc = 0; sc < 8; sc++) s += g_part[((size_t)b * 8 + sc) * ND + d];
    ctx[idx] = s;
}

// ---------------------------------------------------------------------------
extern "C" void kernel_launch(void* const* d_in, const int* in_sizes, int n_in,
                              void* d_out, int out_size) {
    const float* query  = (const float*)d_in[0];
    const float* values = (const float*)d_in[1];
    const float* W1     = (const float*)d_in[2];
    const float* b1     = (const float*)d_in[3];
    const float* W2     = (const float*)d_in[4];
    const float* b2     = (const float*)d_in[5];
    const float* V      = (const float*)d_in[6];
    // d_in[7] = bV: cancels in softmax, unused

    float* ctx  = (float*)d_out;               // [B*D]
    float* attn = (float*)d_out + NB * ND;     // [B*S]

    pq_kernel<<<NB, 256>>>(query, W2, b2, b1);
    score_kernel<<<(NB * NS) / BM, 256>>>(values, W1, V, attn);
    softmax_kernel<<<NB, 256>>>(attn);
    ctx_part_kernel<<<NB * 8 * 4, 128>>>(values, attn);
    ctx_reduce_kernel<<<(NB * ND) / 256, 256>>>(ctx);
}

// round 8
// speedup vs baseline: 1.8252x; 1.8252x over previous
#include <cuda_runtime.h>
#include <cuda_bf16.h>
#include <cstdint>

// BahdanauAttention: B=64, S=2048, D=512, U=256
// score GEMM via mma.sync.m16n8k16 bf16 (hi/lo split, 3 MMAs) — tcgen05 is not
// available on this harness's PTX target (sm_103 without the 'a' feature).

#define NB 64
#define NS 2048
#define ND 512
#define NU 256
#define BS_TOT (NB * NS)

#define BM 128
#define BN 128
#define BK 32
#define NCH (ND / BK)          // 16 k-chunks

#define LDAE 40                // smem row: BK elems + 8 pad (conflict-free ldmatrix)
#define LDAB 80                // bytes per smem row
#define ATILE (BM * LDAB)      // 10240 B
#define BTILE (BN * LDAB)      // 10240 B

// dynamic smem layout
#define oA   0                       // A: [prec][buf] -> 4 * ATILE
#define oB   (4 * ATILE)             // B: [prec][buf] -> 4 * BTILE
#define oPQ  (oB + 4 * BTILE)        // 128 floats
#define oV   (oPQ + 512)             // 128 floats
#define oRB  (oV + 512)              // row partials [128][2]
#define SMEM_BYTES (oRB + 1024)      // 83968

// ---------------- scratch (no allocations allowed) ----------------
__device__ __align__(16) float g_pq[NB * NU];
__device__ __align__(16) float g_sp[2][BS_TOT];            // score partials per u-half
__device__ __align__(16) float g_part[NB * 8 * ND];        // ctx partials
__device__ __align__(16) __nv_bfloat16 g_Whi[NU * ND];     // W1^T hi  [u][k]
__device__ __align__(16) __nv_bfloat16 g_Wlo[NU * ND];     // W1^T lo  [u][k]

// ---------------- helpers ----------------
__device__ __forceinline__ uint32_t smem_u32(const void* p) {
    uint32_t a;
    asm("{ .reg .u64 t; cvta.to.shared.u64 t, %1; cvt.u32.u64 %0, t; }" : "=r"(a) : "l"(p));
    return a;
}
__device__ __forceinline__ void ldsm_x4(uint32_t* r, uint32_t addr) {
    asm volatile("ldmatrix.sync.aligned.m8n8.x4.shared.b16 {%0,%1,%2,%3}, [%4];"
                 : "=r"(r[0]), "=r"(r[1]), "=r"(r[2]), "=r"(r[3]) : "r"(addr));
}
__device__ __forceinline__ void ldsm_x2(uint32_t* r, uint32_t addr) {
    asm volatile("ldmatrix.sync.aligned.m8n8.x2.shared.b16 {%0,%1}, [%2];"
                 : "=r"(r[0]), "=r"(r[1]) : "r"(addr));
}
__device__ __forceinline__ void mma16816(float* c, const uint32_t* a, const uint32_t* b) {
    asm volatile(
        "mma.sync.aligned.m16n8k16.row.col.f32.bf16.bf16.f32 "
        "{%0,%1,%2,%3}, {%4,%5,%6,%7}, {%8,%9}, {%0,%1,%2,%3};"
        : "+f"(c[0]), "+f"(c[1]), "+f"(c[2]), "+f"(c[3])
        : "r"(a[0]), "r"(a[1]), "r"(a[2]), "r"(a[3]), "r"(b[0]), "r"(b[1]));
}
__device__ __forceinline__ void cp_async16(uint32_t dst, const void* src) {
    asm volatile("cp.async.cg.shared.global [%0], [%1], 16;" :: "r"(dst), "l"(src));
}
#define CP_COMMIT() asm volatile("cp.async.commit_group;" ::: "memory")
#define CP_WAIT0()  asm volatile("cp.async.wait_group 0;" ::: "memory")

// split 8 fp32 -> 8 bf16 hi + 8 bf16 lo
__device__ __forceinline__ void split8(float4 v0, float4 v1, uint4& hi, uint4& lo) {
    float x[8] = {v0.x, v0.y, v0.z, v0.w, v1.x, v1.y, v1.z, v1.w};
    __nv_bfloat16 h[8], l[8];
#pragma unroll
    for (int i = 0; i < 8; i++) {
        h[i] = __float2bfloat16(x[i]);
        l[i] = __float2bfloat16(x[i] - __bfloat162float(h[i]));
    }
    __nv_bfloat162 hp[4], lp[4];
#pragma unroll
    for (int i = 0; i < 4; i++) {
        hp[i] = __halves2bfloat162(h[2 * i], h[2 * i + 1]);
        lp[i] = __halves2bfloat162(l[2 * i], l[2 * i + 1]);
    }
    hi = *(uint4*)hp;
    lo = *(uint4*)lp;
}

// ---------------------------------------------------------------------------
// prep: W1 [D,U] fp32 -> g_Whi/g_Wlo [U,D] bf16 (transposed, K-contiguous)
// ---------------------------------------------------------------------------
__global__ void prep_w_kernel(const float* __restrict__ W1) {
    int u = blockIdx.x;
    for (int k = threadIdx.x; k < ND; k += blockDim.x) {
        float x = W1[(size_t)k * NU + u];
        __nv_bfloat16 h = __float2bfloat16(x);
        g_Whi[u * ND + k] = h;
        g_Wlo[u * ND + k] = __float2bfloat16(x - __bfloat162float(h));
    }
}

// ---------------------------------------------------------------------------
// pq[b,u] = query[b,:]@W2[:,u] + b2[u] + b1[u]
// ---------------------------------------------------------------------------
__global__ void pq_kernel(const float* __restrict__ query,
                          const float* __restrict__ W2,
                          const float* __restrict__ b2,
                          const float* __restrict__ b1) {
    __shared__ float q[ND];
    int b = blockIdx.x;
    for (int i = threadIdx.x; i < ND; i += blockDim.x) q[i] = query[b * ND + i];
    __syncthreads();
    int u = threadIdx.x;
    float acc = b2[u] + b1[u];
#pragma unroll 8
    for (int d = 0; d < ND; d++) acc += q[d] * W2[d * NU + u];
    g_pq[b * NU + u] = acc;
}

// ---------------------------------------------------------------------------
// score kernel: HMMA bf16-split GEMM, CTA = 128 rows x 128 u, 8 warps (4Mx2N),
// warp tile 32x64.  grid = (B*S/128) * 2 = 2048.  Fused tanh/V epilogue writes
// per-u-half score partials; softmax merges the two halves.
// ---------------------------------------------------------------------------
__global__ __launch_bounds__(256, 2) void score_mma_kernel(
    const float* __restrict__ values, const float* __restrict__ Vvec,
    float* __restrict__ dummy) {
    extern __shared__ char sm[];
    uint32_t smA = smem_u32(sm);

    int tid = threadIdx.x;
    int wid = tid >> 5, lane = tid & 31;
    int wm = wid & 3, wn = wid >> 2;          // warp grid 4 (M) x 2 (N)
    int l16 = lane & 15;

    int rb = blockIdx.x >> 1;                 // row block
    int nh = blockIdx.x & 1;                  // u half
    int rowBase = rb * BM;
    int b = rowBase / NS;
    int uBase = nh * BN;

    // stage pq (this batch, this u-half) and V
    if (tid < BN) {
        ((float*)(sm + oPQ))[tid] = g_pq[b * NU + uBase + tid];
        ((float*)(sm + oV))[tid] = Vvec[uBase + tid];
    }

    // ldmatrix per-lane base addresses (A: x4 over 16 rows; B: x2 over 8 n-rows)
    uint32_t aLdm = smA + oA + (uint32_t)(wm * 32 + l16) * LDAB + ((lane >> 4) * 16);
    uint32_t bLdm = smA + oB + (uint32_t)(wn * 64 + (l16 & 7)) * LDAB + ((l16 >> 3) * 16);

    // A global: thread -> row tid/2, k-half tid&1 (16 floats per chunk)
    int arow = tid >> 1, ahalf = tid & 1;
    const float* Ab = values + (size_t)(rowBase + arow) * ND + ahalf * 16;
    uint32_t aStOff = (uint32_t)arow * LDAB + ahalf * 32;

    float acc[2][8][4];
#pragma unroll
    for (int mt = 0; mt < 2; mt++)
#pragma unroll
        for (int nt = 0; nt < 8; nt++)
#pragma unroll
            for (int i = 0; i < 4; i++) acc[mt][nt][i] = 0.f;

    // ---- B stage via cp.async (hi+lo), 4 x 16B per thread per chunk ----
    auto stageB = [&](int kc, int buf) {
#pragma unroll
        for (int j = 0; j < 2; j++) {
            int s = tid * 2 + j;             // 0..511
            int u = s >> 2, seg = s & 3;
            size_t ge = (size_t)(uBase + u) * ND + kc * BK + seg * 8;
            uint32_t d = smA + oB + (uint32_t)buf * BTILE + (uint32_t)u * LDAB + seg * 16;
            cp_async16(d, g_Whi + ge);
            cp_async16(d + 2 * BTILE, g_Wlo + ge);
        }
    };

    // ---- prologue: stage chunk 0 ----
    {
        const float* gA = Ab;  // kc = 0
        float4 v0 = *(const float4*)(gA + 0), v1 = *(const float4*)(gA + 4);
        float4 v2 = *(const float4*)(gA + 8), v3 = *(const float4*)(gA + 12);
        uint4 h0, l0, h1, l1;
        split8(v0, v1, h0, l0);
        split8(v2, v3, h1, l1);
        char* pH = sm + oA + aStOff;
        char* pL = sm + oA + 2 * ATILE + aStOff;
        *(uint4*)(pH) = h0; *(uint4*)(pH + 16) = h1;
        *(uint4*)(pL) = l0; *(uint4*)(pL + 16) = l1;
        stageB(0, 0);
        CP_COMMIT();
    }

    for (int kc = 0; kc < NCH; kc++) {
        CP_WAIT0();
        __syncthreads();
        int buf = kc & 1;

        // prefetch next chunk: A -> regs (overlaps compute), B -> cp.async
        float4 p0, p1, p2, p3;
        if (kc + 1 < NCH) {
            const float* gA = Ab + (kc + 1) * BK;
            p0 = *(const float4*)(gA + 0);
            p1 = *(const float4*)(gA + 4);
            p2 = *(const float4*)(gA + 8);
            p3 = *(const float4*)(gA + 12);
            stageB(kc + 1, buf ^ 1);
            CP_COMMIT();
        }

        // ---- compute: 2 k-steps of 16 ----
#pragma unroll
        for (int ks = 0; ks < 2; ks++) {
            uint32_t ah[2][4], al[2][4], bf[8][2];
#pragma unroll
            for (int mt = 0; mt < 2; mt++) {
                uint32_t base = aLdm + (uint32_t)buf * ATILE + mt * 16 * LDAB + ks * 32;
                ldsm_x4(ah[mt], base);
                ldsm_x4(al[mt], base + 2 * ATILE);
            }
#pragma unroll
            for (int nt = 0; nt < 8; nt++)
                ldsm_x2(bf[nt], bLdm + (uint32_t)buf * BTILE + nt * 8 * LDAB + ks * 32);
#pragma unroll
            for (int mt = 0; mt < 2; mt++)
#pragma unroll
                for (int nt = 0; nt < 8; nt++) {
                    mma16816(acc[mt][nt], ah[mt], bf[nt]);   // hi*hi
                    mma16816(acc[mt][nt], al[mt], bf[nt]);   // lo*hi
                }
#pragma unroll
            for (int nt = 0; nt < 8; nt++)
                ldsm_x2(bf[nt], bLdm + 2 * BTILE + (uint32_t)buf * BTILE + nt * 8 * LDAB + ks * 32);
#pragma unroll
            for (int mt = 0; mt < 2; mt++)
#pragma unroll
                for (int nt = 0; nt < 8; nt++)
                    mma16816(acc[mt][nt], ah[mt], bf[nt]);   // hi*lo
        }

        // store prefetched A into the other buffer
        if (kc + 1 < NCH) {
            uint4 h0, l0, h1, l1;
            split8(p0, p1, h0, l0);
            split8(p2, p3, h1, l1);
            char* pH = sm + oA + (buf ^ 1) * ATILE + aStOff;
            char* pL = sm + oA + 2 * ATILE + (buf ^ 1) * ATILE + aStOff;
            *(uint4*)(pH) = h0; *(uint4*)(pH + 16) = h1;
            *(uint4*)(pL) = l0; *(uint4*)(pL + 16) = l1;
        }
    }

    // ---- epilogue: tanh(pv+pq)*V, row-sum over this CTA's 128 u ----
    const float* pqs = (const float*)(sm + oPQ);
    const float* vs = (const float*)(sm + oV);
    float rs[4] = {0.f, 0.f, 0.f, 0.f};   // [mt][rowhalf]
#pragma unroll
    for (int mt = 0; mt < 2; mt++)
#pragma unroll
        for (int nt = 0; nt < 8; nt++) {
            int ul = wn * 64 + nt * 8 + (lane & 3) * 2;
            float p0 = pqs[ul], p1 = pqs[ul + 1];
            float v0 = vs[ul], v1 = vs[ul + 1];
            rs[mt * 2 + 0] += tanhf(acc[mt][nt][0] + p0) * v0 + tanhf(acc[mt][nt][1] + p1) * v1;
            rs[mt * 2 + 1] += tanhf(acc[mt][nt][2] + p0) * v0 + tanhf(acc[mt][nt][3] + p1) * v1;
        }
#pragma unroll
    for (int i = 0; i < 4; i++) {
        rs[i] += __shfl_xor_sync(0xffffffffu, rs[i], 1);
        rs[i] += __shfl_xor_sync(0xffffffffu, rs[i], 2);
    }
    float* rbuf = (float*)(sm + oRB);
    if ((lane & 3) == 0) {
#pragma unroll
        for (int mt = 0; mt < 2; mt++)
#pragma unroll
            for (int h = 0; h < 2; h++) {
                int r = wm * 32 + mt * 16 + h * 8 + (lane >> 2);
                rbuf[r * 2 + wn] = rs[mt * 2 + h];
            }
    }
    __syncthreads();
    if (tid < BM)
        g_sp[nh][rowBase + tid] = rbuf[tid * 2] + rbuf[tid * 2 + 1];
}

// ---------------------------------------------------------------------------
// softmax over S per batch; merges the two u-half score partials.
// ---------------------------------------------------------------------------
__global__ void softmax_kernel(float* __restrict__ attn) {
    __shared__ float red[256];
    int b = blockIdx.x, tid = threadIdx.x;
    size_t base = (size_t)b * NS;
    float v[8];
    float m = -1e30f;
#pragma unroll
    for (int j = 0; j < 8; j++) {
        size_t i = base + tid + j * 256;
        v[j] = g_sp[0][i] + g_sp[1][i];
        m = fmaxf(m, v[j]);
    }
    red[tid] = m;
    __syncthreads();
    for (int o = 128; o > 0; o >>= 1) {
        if (tid < o) red[tid] = fmaxf(red[tid], red[tid + o]);
        __syncthreads();
    }
    m = red[0];
    __syncthreads();
    float s = 0.f;
#pragma unroll
    for (int j = 0; j < 8; j++) {
        v[j] = __expf(v[j] - m);
        s += v[j];
    }
    red[tid] = s;
    __syncthreads();
    for (int o = 128; o > 0; o >>= 1) {
        if (tid < o) red[tid] += red[tid + o];
        __syncthreads();
    }
    float inv = 1.f / red[0];
#pragma unroll
    for (int j = 0; j < 8; j++) attn[base + tid + j * 256] = v[j] * inv;
}

// ---------------------------------------------------------------------------
// context partials + reduce (deterministic, no atomics)
// ---------------------------------------------------------------------------
__global__ __launch_bounds__(128) void ctx_part_kernel(
    const float* __restrict__ values, const float* __restrict__ attn) {
    __shared__ float a[256];
    int blk = blockIdx.x;
    int b = blk >> 5;
    int sc = (blk >> 2) & 7;
    int dc = blk & 3;
    int tid = threadIdx.x;
    a[tid] = attn[(size_t)b * NS + sc * 256 + tid];
    a[tid + 128] = attn[(size_t)b * NS + sc * 256 + tid + 128];
    __syncthreads();
    int d = dc * 128 + tid;
    const float* vp = values + ((size_t)b * NS + (size_t)sc * 256) * ND + d;
    float acc = 0.f;
#pragma unroll 8
    for (int s = 0; s < 256; s++) acc += a[s] * vp[(size_t)s * ND];
    g_part[((size_t)b * 8 + sc) * ND + d] = acc;
}

__global__ void ctx_reduce_kernel(float* __restrict__ ctx) {
    int idx = blockIdx.x * 256 + threadIdx.x;
    int b = idx >> 9, d = idx & 511;
    float s = 0.f;
#pragma unroll
    for (int sc = 0; sc < 8; sc++) s += g_part[((size_t)b * 8 + sc) * ND + d];
    ctx[idx] = s;
}

// ---------------------------------------------------------------------------
extern "C" void kernel_launch(void* const* d_in, const int* in_sizes, int n_in,
                              void* d_out, int out_size) {
    const float* query = (const float*)d_in[0];
    const float* values = (const float*)d_in[1];
    const float* W1 = (const float*)d_in[2];
    const float* b1 = (const float*)d_in[3];
    const float* W2 = (const float*)d_in[4];
    const float* b2 = (const float*)d_in[5];
    const float* V = (const float*)d_in[6];
    // d_in[7] = bV: cancels in softmax

    float* ctx = (float*)d_out;            // [B*D]
    float* attn = (float*)d_out + NB * ND; // [B*S]

    cudaFuncSetAttribute(score_mma_kernel,
                         cudaFuncAttributeMaxDynamicSharedMemorySize, SMEM_BYTES);

    prep_w_kernel<<<NU, 128>>>(W1);
    pq_kernel<<<NB, 256>>>(query, W2, b2, b1);
    score_mma_kernel<<<(BS_TOT / BM) * 2, 256, SMEM_BYTES>>>(values, V, attn);
    softmax_kernel<<<NB, 256>>>(attn);
    ctx_part_kernel<<<NB * 8 * 4, 128>>>(values, attn);
    ctx_reduce_kernel<<<(NB * ND) / 256, 256>>>(ctx);
}

// round 9
// speedup vs baseline: 1.8440x; 1.0103x over previous
#include <cuda_runtime.h>
#include <cuda_bf16.h>
#include <cstdint>

// BahdanauAttention: B=64, S=2048, D=512, U=256
// score GEMM via mma.sync.m16n8k16 bf16 (hi/lo split, 3 MMAs).
// R9: 512 threads/CTA, warp tile 32x32 -> ~80 regs/thread, no spills.

#define NB 64
#define NS 2048
#define ND 512
#define NU 256
#define BS_TOT (NB * NS)

#define BM 128
#define BN 128
#define BK 32
#define NCH (ND / BK)          // 16 k-chunks
#define THREADS 512

#define LDAB 80                // bytes per smem row: 32 bf16 + 8 pad
#define ATILE (BM * LDAB)      // 10240 B
#define BTILE (BN * LDAB)      // 10240 B

// dynamic smem layout
#define oA   0                       // A: [prec][buf] -> 4 * ATILE
#define oB   (4 * ATILE)             // B: [prec][buf] -> 4 * BTILE
#define oPQ  (oB + 4 * BTILE)        // 128 floats
#define oV   (oPQ + 512)             // 128 floats
#define oRB  (oV + 512)              // row partials [128][4]
#define SMEM_BYTES (oRB + 2048)      // 84992

// ---------------- scratch (no allocations allowed) ----------------
__device__ __align__(16) float g_pq[NB * NU];
__device__ __align__(16) float g_sp[2][BS_TOT];            // score partials per u-half
__device__ __align__(16) float g_part[NB * 8 * ND];        // ctx partials
__device__ __align__(16) __nv_bfloat16 g_Whi[NU * ND];     // W1^T hi  [u][k]
__device__ __align__(16) __nv_bfloat16 g_Wlo[NU * ND];     // W1^T lo  [u][k]

// ---------------- helpers ----------------
__device__ __forceinline__ uint32_t smem_u32(const void* p) {
    uint32_t a;
    asm("{ .reg .u64 t; cvta.to.shared.u64 t, %1; cvt.u32.u64 %0, t; }" : "=r"(a) : "l"(p));
    return a;
}
__device__ __forceinline__ void ldsm_x4(uint32_t* r, uint32_t addr) {
    asm volatile("ldmatrix.sync.aligned.m8n8.x4.shared.b16 {%0,%1,%2,%3}, [%4];"
                 : "=r"(r[0]), "=r"(r[1]), "=r"(r[2]), "=r"(r[3]) : "r"(addr));
}
__device__ __forceinline__ void ldsm_x2(uint32_t* r, uint32_t addr) {
    asm volatile("ldmatrix.sync.aligned.m8n8.x2.shared.b16 {%0,%1}, [%2];"
                 : "=r"(r[0]), "=r"(r[1]) : "r"(addr));
}
__device__ __forceinline__ void mma16816(float* c, const uint32_t* a, const uint32_t* b) {
    asm volatile(
        "mma.sync.aligned.m16n8k16.row.col.f32.bf16.bf16.f32 "
        "{%0,%1,%2,%3}, {%4,%5,%6,%7}, {%8,%9}, {%0,%1,%2,%3};"
        : "+f"(c[0]), "+f"(c[1]), "+f"(c[2]), "+f"(c[3])
        : "r"(a[0]), "r"(a[1]), "r"(a[2]), "r"(a[3]), "r"(b[0]), "r"(b[1]));
}
__device__ __forceinline__ void cp_async16(uint32_t dst, const void* src) {
    asm volatile("cp.async.cg.shared.global [%0], [%1], 16;" :: "r"(dst), "l"(src));
}
#define CP_COMMIT() asm volatile("cp.async.commit_group;" ::: "memory")
#define CP_WAIT0()  asm volatile("cp.async.wait_group 0;" ::: "memory")

// split 8 fp32 -> 8 bf16 hi + 8 bf16 lo
__device__ __forceinline__ void split8(float4 v0, float4 v1, uint4& hi, uint4& lo) {
    float x[8] = {v0.x, v0.y, v0.z, v0.w, v1.x, v1.y, v1.z, v1.w};
    __nv_bfloat16 h[8], l[8];
#pragma unroll
    for (int i = 0; i < 8; i++) {
        h[i] = __float2bfloat16(x[i]);
        l[i] = __float2bfloat16(x[i] - __bfloat162float(h[i]));
    }
    __nv_bfloat162 hp[4], lp[4];
#pragma unroll
    for (int i = 0; i < 4; i++) {
        hp[i] = __halves2bfloat162(h[2 * i], h[2 * i + 1]);
        lp[i] = __halves2bfloat162(l[2 * i], l[2 * i + 1]);
    }
    hi = *(uint4*)hp;
    lo = *(uint4*)lp;
}

// ---------------------------------------------------------------------------
// prep: W1 [D,U] fp32 -> g_Whi/g_Wlo [U,D] bf16 (transposed, K-contiguous)
// ---------------------------------------------------------------------------
__global__ void prep_w_kernel(const float* __restrict__ W1) {
    int u = blockIdx.x;
    for (int k = threadIdx.x; k < ND; k += blockDim.x) {
        float x = W1[(size_t)k * NU + u];
        __nv_bfloat16 h = __float2bfloat16(x);
        g_Whi[u * ND + k] = h;
        g_Wlo[u * ND + k] = __float2bfloat16(x - __bfloat162float(h));
    }
}

// ---------------------------------------------------------------------------
// pq[b,u] = query[b,:]@W2[:,u] + b2[u] + b1[u]
// ---------------------------------------------------------------------------
__global__ void pq_kernel(const float* __restrict__ query,
                          const float* __restrict__ W2,
                          const float* __restrict__ b2,
                          const float* __restrict__ b1) {
    __shared__ float q[ND];
    int b = blockIdx.x;
    for (int i = threadIdx.x; i < ND; i += blockDim.x) q[i] = query[b * ND + i];
    __syncthreads();
    int u = threadIdx.x;
    float acc = b2[u] + b1[u];
#pragma unroll 8
    for (int d = 0; d < ND; d++) acc += q[d] * W2[d * NU + u];
    g_pq[b * NU + u] = acc;
}

// ---------------------------------------------------------------------------
// score kernel: HMMA bf16-split GEMM, CTA = 128 rows x 128 u, 16 warps (4Mx4N),
// warp tile 32x32.  grid = (B*S/128) * 2.  Fused tanh/V epilogue writes
// per-u-half score partials; softmax merges the two halves.
// ---------------------------------------------------------------------------
__global__ __launch_bounds__(THREADS, 1) void score_mma_kernel(
    const float* __restrict__ values, const float* __restrict__ Vvec,
    float* __restrict__ dummy) {
    extern __shared__ char sm[];
    uint32_t smA = smem_u32(sm);

    int tid = threadIdx.x;
    int wid = tid >> 5, lane = tid & 31;
    int wm = wid & 3, wn = wid >> 2;          // warp grid 4 (M) x 4 (N)
    int l16 = lane & 15;

    int rb = blockIdx.x >> 1;                 // row block
    int nh = blockIdx.x & 1;                  // u half
    int rowBase = rb * BM;
    int b = rowBase / NS;
    int uBase = nh * BN;

    // stage pq (this batch, this u-half) and V
    if (tid < BN) {
        ((float*)(sm + oPQ))[tid] = g_pq[b * NU + uBase + tid];
        ((float*)(sm + oV))[tid] = Vvec[uBase + tid];
    }

    // ldmatrix per-lane base addresses (A: x4 over 16 rows; B: x2 over 8 n-rows)
    uint32_t aLdm = smA + oA + (uint32_t)(wm * 32 + l16) * LDAB + ((lane >> 4) * 16);
    uint32_t bLdm = smA + oB + (uint32_t)(wn * 32 + (l16 & 7)) * LDAB + ((l16 >> 3) * 16);

    // A global: thread -> row tid/4, k-quarter tid&3 (8 floats per chunk)
    int arow = tid >> 2, aq = tid & 3;
    const float* Ab = values + (size_t)(rowBase + arow) * ND + aq * 8;
    uint32_t aStOff = (uint32_t)arow * LDAB + aq * 16;

    float acc[2][4][4];
#pragma unroll
    for (int mt = 0; mt < 2; mt++)
#pragma unroll
        for (int nt = 0; nt < 4; nt++)
#pragma unroll
            for (int i = 0; i < 4; i++) acc[mt][nt][i] = 0.f;

    // ---- B stage via cp.async (hi+lo), 2 x 16B per thread per chunk ----
    auto stageB = [&](int kc, int buf) {
        int u = tid >> 2, seg = tid & 3;          // 512 threads = 512 segs
        size_t ge = (size_t)(uBase + u) * ND + kc * BK + seg * 8;
        uint32_t d = smA + oB + (uint32_t)buf * BTILE + (uint32_t)u * LDAB + seg * 16;
        cp_async16(d, g_Whi + ge);
        cp_async16(d + 2 * BTILE, g_Wlo + ge);
    };

    // ---- prologue: stage chunk 0 ----
    {
        float4 v0 = *(const float4*)(Ab + 0), v1 = *(const float4*)(Ab + 4);
        uint4 h0, l0;
        split8(v0, v1, h0, l0);
        *(uint4*)(sm + oA + aStOff) = h0;
        *(uint4*)(sm + oA + 2 * ATILE + aStOff) = l0;
        stageB(0, 0);
        CP_COMMIT();
    }

    for (int kc = 0; kc < NCH; kc++) {
        CP_WAIT0();
        __syncthreads();
        int buf = kc & 1;

        // prefetch next chunk: A -> regs (8 floats), B -> cp.async
        float4 p0, p1;
        if (kc + 1 < NCH) {
            const float* gA = Ab + (kc + 1) * BK;
            p0 = *(const float4*)(gA + 0);
            p1 = *(const float4*)(gA + 4);
            stageB(kc + 1, buf ^ 1);
            CP_COMMIT();
        }

        // ---- compute: 2 k-steps of 16 ----
#pragma unroll
        for (int ks = 0; ks < 2; ks++) {
            uint32_t ah[2][4], al[2][4], bf[4][2];
#pragma unroll
            for (int mt = 0; mt < 2; mt++) {
                uint32_t base = aLdm + (uint32_t)buf * ATILE + mt * 16 * LDAB + ks * 32;
                ldsm_x4(ah[mt], base);
                ldsm_x4(al[mt], base + 2 * ATILE);
            }
#pragma unroll
            for (int nt = 0; nt < 4; nt++)
                ldsm_x2(bf[nt], bLdm + (uint32_t)buf * BTILE + nt * 8 * LDAB + ks * 32);
#pragma unroll
            for (int mt = 0; mt < 2; mt++)
#pragma unroll
                for (int nt = 0; nt < 4; nt++) {
                    mma16816(acc[mt][nt], ah[mt], bf[nt]);   // hi*hi
                    mma16816(acc[mt][nt], al[mt], bf[nt]);   // lo*hi
                }
#pragma unroll
            for (int nt = 0; nt < 4; nt++)
                ldsm_x2(bf[nt], bLdm + 2 * BTILE + (uint32_t)buf * BTILE + nt * 8 * LDAB + ks * 32);
#pragma unroll
            for (int mt = 0; mt < 2; mt++)
#pragma unroll
                for (int nt = 0; nt < 4; nt++)
                    mma16816(acc[mt][nt], ah[mt], bf[nt]);   // hi*lo
        }

        // store prefetched A into the other buffer
        if (kc + 1 < NCH) {
            uint4 h0, l0;
            split8(p0, p1, h0, l0);
            *(uint4*)(sm + oA + (buf ^ 1) * ATILE + aStOff) = h0;
            *(uint4*)(sm + oA + 2 * ATILE + (buf ^ 1) * ATILE + aStOff) = l0;
        }
    }

    // ---- epilogue: tanh(pv+pq)*V, row-sum over this CTA's 128 u ----
    const float* pqs = (const float*)(sm + oPQ);
    const float* vs = (const float*)(sm + oV);
    float rs[4] = {0.f, 0.f, 0.f, 0.f};   // [mt][rowhalf]
#pragma unroll
    for (int mt = 0; mt < 2; mt++)
#pragma unroll
        for (int nt = 0; nt < 4; nt++) {
            int ul = wn * 32 + nt * 8 + (lane & 3) * 2;
            float p0 = pqs[ul], p1 = pqs[ul + 1];
            float v0 = vs[ul], v1 = vs[ul + 1];
            rs[mt * 2 + 0] += tanhf(acc[mt][nt][0] + p0) * v0 + tanhf(acc[mt][nt][1] + p1) * v1;
            rs[mt * 2 + 1] += tanhf(acc[mt][nt][2] + p0) * v0 + tanhf(acc[mt][nt][3] + p1) * v1;
        }
#pragma unroll
    for (int i = 0; i < 4; i++) {
        rs[i] += __shfl_xor_sync(0xffffffffu, rs[i], 1);
        rs[i] += __shfl_xor_sync(0xffffffffu, rs[i], 2);
    }
    float* rbuf = (float*)(sm + oRB);
    if ((lane & 3) == 0) {
#pragma unroll
        for (int mt = 0; mt < 2; mt++)
#pragma unroll
            for (int h = 0; h < 2; h++) {
                int r = wm * 32 + mt * 16 + h * 8 + (lane >> 2);
                rbuf[r * 4 + wn] = rs[mt * 2 + h];
            }
    }
    __syncthreads();
    if (tid < BM)
        g_sp[nh][rowBase + tid] =
            (rbuf[tid * 4] + rbuf[tid * 4 + 1]) + (rbuf[tid * 4 + 2] + rbuf[tid * 4 + 3]);
}

// ---------------------------------------------------------------------------
// softmax over S per batch; merges the two u-half score partials.
// ---------------------------------------------------------------------------
__global__ void softmax_kernel(float* __restrict__ attn) {
    __shared__ float red[256];
    int b = blockIdx.x, tid = threadIdx.x;
    size_t base = (size_t)b * NS;
    float v[8];
    float m = -1e30f;
#pragma unroll
    for (int j = 0; j < 8; j++) {
        size_t i = base + tid + j * 256;
        v[j] = g_sp[0][i] + g_sp[1][i];
        m = fmaxf(m, v[j]);
    }
    red[tid] = m;
    __syncthreads();
    for (int o = 128; o > 0; o >>= 1) {
        if (tid < o) red[tid] = fmaxf(red[tid], red[tid + o]);
        __syncthreads();
    }
    m = red[0];
    __syncthreads();
    float s = 0.f;
#pragma unroll
    for (int j = 0; j < 8; j++) {
        v[j] = __expf(v[j] - m);
        s += v[j];
    }
    red[tid] = s;
    __syncthreads();
    for (int o = 128; o > 0; o >>= 1) {
        if (tid < o) red[tid] += red[tid + o];
        __syncthreads();
    }
    float inv = 1.f / red[0];
#pragma unroll
    for (int j = 0; j < 8; j++) attn[base + tid + j * 256] = v[j] * inv;
}

// ---------------------------------------------------------------------------
// context partials + reduce (deterministic, no atomics)
// ---------------------------------------------------------------------------
__global__ __launch_bounds__(128) void ctx_part_kernel(
    const float* __restrict__ values, const float* __restrict__ attn) {
    __shared__ float a[256];
    int blk = blockIdx.x;
    int b = blk >> 5;
    int sc = (blk >> 2) & 7;
    int dc = blk & 3;
    int tid = threadIdx.x;
    a[tid] = attn[(size_t)b * NS + sc * 256 + tid];
    a[tid + 128] = attn[(size_t)b * NS + sc * 256 + tid + 128];
    __syncthreads();
    int d = dc * 128 + tid;
    const float* vp = values + ((size_t)b * NS + (size_t)sc * 256) * ND + d;
    float acc = 0.f;
#pragma unroll 8
    for (int s = 0; s < 256; s++) acc += a[s] * vp[(size_t)s * ND];
    g_part[((size_t)b * 8 + sc) * ND + d] = acc;
}

__global__ void ctx_reduce_kernel(float* __restrict__ ctx) {
    int idx = blockIdx.x * 256 + threadIdx.x;
    int b = idx >> 9, d = idx & 511;
    float s = 0.f;
#pragma unroll
    for (int sc = 0; sc < 8; sc++) s += g_part[((size_t)b * 8 + sc) * ND + d];
    ctx[idx] = s;
}

// ---------------------------------------------------------------------------
extern "C" void kernel_launch(void* const* d_in, const int* in_sizes, int n_in,
                              void* d_out, int out_size) {
    const float* query = (const float*)d_in[0];
    const float* values = (const float*)d_in[1];
    const float* W1 = (const float*)d_in[2];
    const float* b1 = (const float*)d_in[3];
    const float* W2 = (const float*)d_in[4];
    const float* b2 = (const float*)d_in[5];
    const float* V = (const float*)d_in[6];
    // d_in[7] = bV: cancels in softmax

    float* ctx = (float*)d_out;            // [B*D]
    float* attn = (float*)d_out + NB * ND; // [B*S]

    cudaFuncSetAttribute(score_mma_kernel,
                         cudaFuncAttributeMaxDynamicSharedMemorySize, SMEM_BYTES);

    prep_w_kernel<<<NU, 128>>>(W1);
    pq_kernel<<<NB, 256>>>(query, W2, b2, b1);
    score_mma_kernel<<<(BS_TOT / BM) * 2, THREADS, SMEM_BYTES>>>(values, V, attn);
    softmax_kernel<<<NB, 256>>>(attn);
    ctx_part_kernel<<<NB * 8 * 4, 128>>>(values, attn);
    ctx_reduce_kernel<<<(NB * ND) / 256, 256>>>(ctx);
}